// round 12
// baseline (speedup 1.0000x reference)
#include <cuda_runtime.h>
#include <cuda_bf16.h>
#include <stdint.h>

#define HD 1024
#define TT 4096
#define NB0 32
#define NB12 57
#define GRIDN (NB0 + 2*NB12)   /* 146 persistent blocks */
#define NTHR 384
#define NW 12                  /* warps per block */

#define OFF1 (NB0*128*1024)            /* 4194304  */
#define SEG12 (NB12*72*2048)           /* 8404992  */
#define OFF2 (OFF1 + SEG12)
#define WTOT (OFF1 + 2*SEG12)          /* 21004288 */

#define DSMEM_BYTES 196608             /* l12: 48 rows*4KB ; l0: 80 rows*2KB */

// ---------------- static device storage (no allocations) ----------------
__device__ __align__(16) __nv_bfloat16 g_wblob[WTOT];            // ~42 MB bf16 weights
__device__ float g_bias[NB0*128 + 2*NB12*72];
__device__ float g_wih0[NB0*128*2];
__device__ __align__(16) __nv_bfloat16 g_hall[(size_t)(TT+1)*3*HD]; // h history, write-once
__device__ __align__(128) int g_flag[3*64*32];                   // one 128B line per (layer,block)

__device__ __forceinline__ __nv_bfloat162 u2b(unsigned u) {
    return *reinterpret_cast<const __nv_bfloat162*>(&u);
}
__device__ __forceinline__ float sigm(float v)  { return __fdividef(1.0f, 1.0f + __expf(-v)); }
__device__ __forceinline__ float ftanh(float v) {
    v = fminf(fmaxf(v, -30.0f), 30.0f);
    float e = __expf(2.0f*v);
    return __fdividef(e - 1.0f, e + 1.0f);
}
__device__ __forceinline__ int ld_acq(const int* p) {
    int v; asm volatile("ld.acquire.gpu.s32 %0, [%1];" : "=r"(v) : "l"(p) : "memory"); return v;
}
__device__ __forceinline__ void st_rel(int* p, int v) {
    asm volatile("st.release.gpu.s32 [%0], %1;" :: "l"(p), "r"(v) : "memory");
}

// whole-warp wait: padded flags (stride 32 ints = 128B), each lane owns <=2 flags
__device__ __forceinline__ void wait_flags_pad(const int* base, int nb, int target, int lane) {
    const int* p0 = base + (size_t)(lane < nb ? lane : 0)*32;
    const int* p1 = base + (size_t)((lane + 32 < nb) ? (lane + 32) : 0)*32;
    for (;;) {
        int v = min(ld_acq(p0), ld_acq(p1));
        if (__all_sync(0xffffffffu, v >= target)) break;
    }
}

// ---------------- prep: repack weights into per-block bf16 blobs ----------------
__global__ void prep_w(const float* __restrict__ Whh0,
                       const float* __restrict__ Wih12,
                       const float* __restrict__ Whh12)
{
    for (long long i = (long long)blockIdx.x*blockDim.x + threadIdx.x; i < (long long)WTOT;
         i += (long long)gridDim.x*blockDim.x) {
        float val;
        if (i < (long long)OFF1) {
            int b   = (int)(i >> 17);
            int rem = (int)(i & 131071);
            int r   = rem >> 10;
            int col = rem & 1023;
            int grow = (r & 3)*HD + b*32 + (r >> 2);
            val = Whh0[(long long)grow*1024 + col];
        } else {
            int l = (i < (long long)OFF2) ? 0 : 1;
            long long j = i - (l ? (long long)OFF2 : (long long)OFF1);
            int b   = (int)(j / 147456);
            int rem = (int)(j % 147456);
            int r   = rem >> 11;
            int col = rem & 2047;
            int ih  = r >> 2;
            int CHb = (b == NB12-1) ? 16 : 18;
            if (ih >= CHb) val = 0.0f;
            else {
                int grow = (r & 3)*HD + b*18 + ih;
                if (col < 1024) val = Wih12[(long long)l*4194304 + (long long)grow*1024 + col];
                else            val = Whh12[(long long)l*4194304 + (long long)grow*1024 + (col-1024)];
            }
        }
        g_wblob[i] = __float2bfloat16(val);
    }
}

// ---------------- prep: biases, W_ih0, state/flag reset ----------------
__global__ void prep_small(const float* __restrict__ Wih0,
                           const float* __restrict__ bih0, const float* __restrict__ bhh0,
                           const float* __restrict__ bih12, const float* __restrict__ bhh12)
{
    int i = blockIdx.x*blockDim.x + threadIdx.x;
    int n = blockDim.x*gridDim.x;
    for (int k = i; k < 3*64*32; k += n) g_flag[k] = 0;
    for (int k = i; k < 3*HD; k += n) g_hall[k] = __float2bfloat16(0.0f);
    for (int k = i; k < NB0*128 + 2*NB12*72; k += n) {
        float v;
        if (k < NB0*128) {
            int b = k >> 7, r = k & 127;
            int grow = (r & 3)*HD + b*32 + (r >> 2);
            v = bih0[grow] + bhh0[grow];
        } else {
            int j  = k - NB0*128;
            int l  = j / (NB12*72);
            int jj = j - l*(NB12*72);
            int b  = jj / 72, r = jj % 72;
            int ih = r >> 2;
            int CHb = (b == NB12-1) ? 16 : 18;
            if (ih >= CHb) v = 0.0f;
            else {
                int grow = (r & 3)*HD + b*18 + ih;
                v = bih12[l*4096 + grow] + bhh12[l*4096 + grow];
            }
        }
        g_bias[k] = v;
    }
    for (int k = i; k < NB0*128*2; k += n) {
        int b = k >> 8;
        int r = (k >> 1) & 127;
        int c = k & 1;
        int grow = (r & 3)*HD + b*32 + (r >> 2);
        g_wih0[k] = Wih0[grow*2 + c];
    }
}

// ---------------- dot-product primitives (bf16x2 HFMA2) ----------------
template<int NJ>
__device__ __forceinline__ float dot_rr(const uint4* __restrict__ w, const uint4* __restrict__ v)
{
    __nv_bfloat162 z = __floats2bfloat162_rn(0.0f, 0.0f);
    __nv_bfloat162 a0 = z, a1 = z, a2 = z, a3 = z;
#pragma unroll
    for (int j = 0; j < NJ; j++) {
        a0 = __hfma2(u2b(w[j].x), u2b(v[j].x), a0);
        a1 = __hfma2(u2b(w[j].y), u2b(v[j].y), a1);
        a2 = __hfma2(u2b(w[j].z), u2b(v[j].z), a2);
        a3 = __hfma2(u2b(w[j].w), u2b(v[j].w), a3);
    }
    __nv_bfloat162 s2 = __hadd2(__hadd2(a0, a1), __hadd2(a2, a3));
    float2 f = __bfloat1622float2(s2);
    return f.x + f.y;
}

template<int NJ>
__device__ __forceinline__ float dot_sm(const uint4* __restrict__ wbase, int lane, const uint4* __restrict__ v)
{
    __nv_bfloat162 z = __floats2bfloat162_rn(0.0f, 0.0f);
    __nv_bfloat162 a0 = z, a1 = z, a2 = z, a3 = z;
#pragma unroll
    for (int j = 0; j < NJ; j++) {
        uint4 w = wbase[j*32 + lane];
        a0 = __hfma2(u2b(w.x), u2b(v[j].x), a0);
        a1 = __hfma2(u2b(w.y), u2b(v[j].y), a1);
        a2 = __hfma2(u2b(w.z), u2b(v[j].z), a2);
        a3 = __hfma2(u2b(w.w), u2b(v[j].w), a3);
    }
    __nv_bfloat162 s2 = __hadd2(__hadd2(a0, a1), __hadd2(a2, a3));
    float2 f = __bfloat1622float2(s2);
    return f.x + f.y;
}

// ---------------- persistent dataflow LSTM kernel (fused epilogue) ----------------
__global__ void __launch_bounds__(NTHR, 1) lstm_main(const float* __restrict__ x)
{
    extern __shared__ uint4 s_w4[];     // cached weight rows (per-warp slots)
    __shared__ uint4 s_v4[256];         // staged input vector (up to 2048 bf16)

    const int tid = threadIdx.x, lane = tid & 31, wid = tid >> 5;
    const int b = blockIdx.x;
    int layer, idx;
    if (b < NB0)             { layer = 0; idx = b; }
    else if (b < NB0+NB12)   { layer = 1; idx = b - NB0; }
    else                     { layer = 2; idx = b - (NB0+NB12); }

    int CH, chglob, NBown, NBlow, boff;
    long long woff;
    if (layer == 0) {
        CH = 32; chglob = idx*32;
        woff = (long long)idx*131072; boff = idx*128;
        NBown = NB0; NBlow = 0;
    } else {
        CH = (idx == NB12-1) ? 16 : 18; chglob = idx*18;
        woff = (long long)OFF1 + (long long)(layer-1)*SEG12 + (long long)idx*147456;
        boff = NB0*128 + (layer-1)*(NB12*72) + idx*72;
        NBown = NB12; NBlow = (layer == 1) ? NB0 : NB12;
    }
    const uint4* gw = (const uint4*)(g_wblob + woff);
    const uint4* hall4 = (const uint4*)g_hall;
    int* ownflags = &g_flag[layer*64*32];
    int* lowflags = &g_flag[(layer-1)*64*32];

    // ---- channel-aligned warp ownership ----
    int nch, c0, sbase;   // channels this warp owns; first channel; smem slot base
    if (layer == 0) {
        // 8 warps x3ch + 4 warps x2ch = 32
        nch = (wid < 8) ? 3 : 2;
        c0  = (wid < 8) ? 3*wid : 24 + 2*(wid - 8);
        sbase = (wid < 8) ? 8*wid : 64 + 4*(wid - 8);   // 4*(nch-1) slots per warp
    } else {
        int extra = CH - 12;                 // 6 (CH=18) or 4 (CH=16)
        nch = 1 + (wid < extra ? 1 : 0);
        c0  = wid + min(wid, extra);
        sbase = (wid < extra) ? 6*wid : 6*extra + 2*(wid - extra); // 4*nch-2 slots
    }
    const int rows = 4*nch;

    // ---- one-time weight staging ----
    uint4 wreg[16];
    if (layer == 0) {
        // register rows: first channel's 4 rows
#pragma unroll
        for (int k = 0; k < 4; k++)
#pragma unroll
            for (int j = 0; j < 4; j++)
                wreg[k*4+j] = gw[(size_t)(4*c0 + k)*128 + j*32 + lane];
        // smem rows: channels 1..nch-1
        for (int k = 4; k < rows; k++) {
            int gr = 4*(c0 + (k >> 2)) + (k & 3);
#pragma unroll
            for (int j = 0; j < 4; j++)
                s_w4[(size_t)(sbase + k - 4)*128 + j*32 + lane] = gw[(size_t)gr*128 + j*32 + lane];
        }
    } else {
        // register rows: first channel's rows 0,1
#pragma unroll
        for (int k = 0; k < 2; k++)
#pragma unroll
            for (int j = 0; j < 8; j++)
                wreg[k*8+j] = gw[(size_t)(4*c0 + k)*256 + j*32 + lane];
        // smem rows: rest
        for (int k = 2; k < rows; k++) {
            int gr = 4*(c0 + (k >> 2)) + (k & 3);
#pragma unroll
            for (int j = 0; j < 8; j++)
                s_w4[(size_t)(sbase + k - 2)*256 + j*32 + lane] = gw[(size_t)gr*256 + j*32 + lane];
        }
    }
    // per-lane channel constants: lane j < nch owns channel c0 + j
    float4 bj = make_float4(0.f,0.f,0.f,0.f), wxa = bj, wxb = bj;
    float creg = 0.0f;
    if (lane < nch) {
        int lrow = 4*(c0 + lane);
        bj = *(const float4*)&g_bias[boff + lrow];
        if (layer == 0) {
            wxa = *(const float4*)&g_wih0[idx*256 + lrow*2];
            wxb = *(const float4*)&g_wih0[idx*256 + lrow*2 + 4];
        }
    }
    __syncthreads();

    for (int t = 0; t < TT; ++t) {
        float x0 = 0.0f, x1 = 0.0f;
        if (layer == 0) { x0 = __ldg(&x[2*t]); x1 = __ldg(&x[2*t + 1]); }

        // ---- poll + stage (warps 0/1 only) ----
        if (layer == 0) {
            if (wid == 0) {
                wait_flags_pad(ownflags, NBown, t, lane);
                size_t ho = (size_t)t*384;
                s_v4[lane]      = hall4[ho + lane];
                s_v4[lane + 32] = hall4[ho + lane + 32];
                s_v4[lane + 64] = hall4[ho + lane + 64];
                s_v4[lane + 96] = hall4[ho + lane + 96];
            }
        } else {
            if (wid == 0) {
                wait_flags_pad(lowflags, NBlow, t + 1, lane);
                size_t lo = (size_t)(t+1)*384 + (size_t)(layer-1)*128;
                s_v4[lane]      = hall4[lo + lane];
                s_v4[lane + 32] = hall4[lo + lane + 32];
                s_v4[lane + 64] = hall4[lo + lane + 64];
                s_v4[lane + 96] = hall4[lo + lane + 96];
            } else if (wid == 1) {
                wait_flags_pad(ownflags, NBown, t, lane);
                size_t ho = (size_t)t*384 + (size_t)layer*128;
                s_v4[128 + lane]      = hall4[ho + lane];
                s_v4[128 + lane + 32] = hall4[ho + lane + 32];
                s_v4[128 + lane + 64] = hall4[ho + lane + 64];
                s_v4[128 + lane + 96] = hall4[ho + lane + 96];
            }
        }
        __syncthreads();   // A: deps satisfied + vector staged

        // ---- dots + fused epilogue ----
        if (layer == 0) {
            uint4 vv[4];
#pragma unroll
            for (int j = 0; j < 4; j++) vv[j] = s_v4[j*32 + lane];
            float ss[12];
#pragma unroll
            for (int k = 0; k < 4; k++)
                ss[k] = dot_rr<4>(&wreg[k*4], vv);
#pragma unroll
            for (int k = 4; k < 12; k++)
                ss[k] = (k < rows) ? dot_sm<4>(s_w4 + (size_t)(sbase + k - 4)*128, lane, vv) : 0.0f;
#pragma unroll
            for (int o = 16; o; o >>= 1)
#pragma unroll
                for (int k = 0; k < 12; k++)
                    if (k < rows) ss[k] += __shfl_xor_sync(0xffffffffu, ss[k], o);
            if (lane < nch) {
                float gi = ss[0], gf = ss[1], gg = ss[2], go = ss[3];
                if (lane == 1) { gi = ss[4]; gf = ss[5]; gg = ss[6];  go = ss[7]; }
                if (lane == 2) { gi = ss[8]; gf = ss[9]; gg = ss[10]; go = ss[11]; }
                gi += bj.x + wxa.x*x0 + wxa.y*x1;
                gf += bj.y + wxa.z*x0 + wxa.w*x1;
                gg += bj.z + wxb.x*x0 + wxb.y*x1;
                go += bj.w + wxb.z*x0 + wxb.w*x1;
                float c = sigm(gf)*creg + sigm(gi)*ftanh(gg);
                creg = c;
                g_hall[(size_t)(t+1)*3072 + chglob + c0 + lane] =
                    __float2bfloat16(sigm(go)*ftanh(c));
            }
        } else {
            uint4 vv[8];
#pragma unroll
            for (int j = 0; j < 8; j++) vv[j] = s_v4[j*32 + lane];
            float ss[8];
            ss[0] = dot_rr<8>(&wreg[0], vv);
            ss[1] = dot_rr<8>(&wreg[8], vv);
#pragma unroll
            for (int k = 2; k < 8; k++)
                ss[k] = (k < rows) ? dot_sm<8>(s_w4 + (size_t)(sbase + k - 2)*256, lane, vv) : 0.0f;
#pragma unroll
            for (int o = 16; o; o >>= 1)
#pragma unroll
                for (int k = 0; k < 8; k++)
                    if (k < rows) ss[k] += __shfl_xor_sync(0xffffffffu, ss[k], o);
            if (lane < nch) {
                float gi = ss[0], gf = ss[1], gg = ss[2], go = ss[3];
                if (lane == 1) { gi = ss[4]; gf = ss[5]; gg = ss[6]; go = ss[7]; }
                gi += bj.x; gf += bj.y; gg += bj.z; go += bj.w;
                float c = sigm(gf)*creg + sigm(gi)*ftanh(gg);
                creg = c;
                g_hall[(size_t)(t+1)*3072 + (size_t)layer*1024 + chglob + c0 + lane] =
                    __float2bfloat16(sigm(go)*ftanh(c));
            }
        }
        __syncthreads();   // B: all h stores done

        // ---- publish (single thread, cumulativity via fence) ----
        if (tid == 0) {
            __threadfence();
            st_rel(&ownflags[idx*32], t + 1);
        }
    }
}

// ---------------- output head ----------------
__global__ void finalize_k(const float* __restrict__ Wres, const float* __restrict__ bres,
                           float* __restrict__ out)
{
    __shared__ float sred[4];
    const int t = blockIdx.x;
    const int tid = threadIdx.x;
    const __nv_bfloat16* h = g_hall + (size_t)(t+1)*3072 + 2048;
    float s = 0.0f;
    for (int k = tid; k < HD; k += 128) s += __bfloat162float(h[k]) * Wres[k];
#pragma unroll
    for (int o = 16; o; o >>= 1) s += __shfl_xor_sync(0xffffffffu, s, o);
    if ((tid & 31) == 0) sred[tid >> 5] = s;
    __syncthreads();
    if (tid == 0) {
        float tot = sred[0] + sred[1] + sred[2] + sred[3];
        out[t] = 1.0f/(1.0f + __expf(-(tot + bres[0])));
    }
}

// ---------------- launch ----------------
extern "C" void kernel_launch(void* const* d_in, const int* in_sizes, int n_in,
                              void* d_out, int out_size)
{
    const float* x     = (const float*)d_in[0];
    const float* Wih0  = (const float*)d_in[1];
    const float* Whh0  = (const float*)d_in[2];
    const float* bih0  = (const float*)d_in[3];
    const float* bhh0  = (const float*)d_in[4];
    const float* Wih12 = (const float*)d_in[5];
    const float* Whh12 = (const float*)d_in[6];
    const float* bih12 = (const float*)d_in[7];
    const float* bhh12 = (const float*)d_in[8];
    const float* Wres  = (const float*)d_in[9];
    const float* bres  = (const float*)d_in[10];
    float* out = (float*)d_out;

    cudaFuncSetAttribute(lstm_main, cudaFuncAttributeMaxDynamicSharedMemorySize, DSMEM_BYTES);

    prep_small<<<26, 256>>>(Wih0, bih0, bhh0, bih12, bhh12);
    prep_w<<<2048, 256>>>(Whh0, Wih12, Whh12);
    lstm_main<<<GRIDN, NTHR, DSMEM_BYTES>>>(x);
    finalize_k<<<TT, 128>>>(Wres, bres, out);
}

// round 16
// speedup vs baseline: 1.3139x; 1.3139x over previous
#include <cuda_runtime.h>
#include <cuda_bf16.h>
#include <stdint.h>

#define HD 1024
#define TT 4096
#define NB0 32
#define NB12 57
#define GRIDN (NB0 + 2*NB12)   /* 146 persistent blocks */
#define NTHR 384
#define NW 12                  /* warps per block */

#define OFF1 (NB0*128*1024)            /* 4194304  */
#define SEG12 (NB12*72*2048)           /* 8404992  */
#define OFF2 (OFF1 + SEG12)
#define WTOT (OFF1 + 2*SEG12)          /* 21004288 */

#define DSMEM_BYTES 147456             /* l12: 36 rows*4KB ; l0: 56 rows*2KB=112KB */

// ---------------- static device storage (no allocations) ----------------
__device__ __align__(16) __nv_bfloat16 g_wblob[WTOT];            // ~42 MB bf16 weights
__device__ float g_bias[NB0*128 + 2*NB12*72];
__device__ float g_wih0[NB0*128*2];
__device__ __align__(16) __nv_bfloat16 g_hall[(size_t)(TT+1)*3*HD]; // h history, write-once
__device__ __align__(128) int g_flag[3*64*32];                   // one 128B line per (layer,block)

__device__ __forceinline__ __nv_bfloat162 u2b(unsigned u) {
    return *reinterpret_cast<const __nv_bfloat162*>(&u);
}
__device__ __forceinline__ float sigm(float v)  { return __fdividef(1.0f, 1.0f + __expf(-v)); }
__device__ __forceinline__ float ftanh(float v) {
    v = fminf(fmaxf(v, -30.0f), 30.0f);
    float e = __expf(2.0f*v);
    return __fdividef(e - 1.0f, e + 1.0f);
}
__device__ __forceinline__ int ld_acq(const int* p) {
    int v; asm volatile("ld.acquire.gpu.s32 %0, [%1];" : "=r"(v) : "l"(p) : "memory"); return v;
}
__device__ __forceinline__ void st_rel(int* p, int v) {
    asm volatile("st.release.gpu.s32 [%0], %1;" :: "l"(p), "r"(v) : "memory");
}

// whole-warp wait on flags [first, first+cnt): ONE acquire load per lane per spin.
// cnt must be <= 32 and >= 1; lanes >= cnt re-poll flag 'first'.
__device__ __forceinline__ void wait_flags_sub(const int* base, int first, int cnt,
                                               int target, int lane) {
    const int* p = base + (size_t)(first + ((lane < cnt) ? lane : 0))*32;
    for (;;) {
        int v = ld_acq(p);
        if (__all_sync(0xffffffffu, v >= target)) break;
    }
}

// ---------------- prep: repack weights into per-block bf16 blobs ----------------
__global__ void prep_w(const float* __restrict__ Whh0,
                       const float* __restrict__ Wih12,
                       const float* __restrict__ Whh12)
{
    for (long long i = (long long)blockIdx.x*blockDim.x + threadIdx.x; i < (long long)WTOT;
         i += (long long)gridDim.x*blockDim.x) {
        float val;
        if (i < (long long)OFF1) {
            int b   = (int)(i >> 17);
            int rem = (int)(i & 131071);
            int r   = rem >> 10;
            int col = rem & 1023;
            int grow = (r & 3)*HD + b*32 + (r >> 2);
            val = Whh0[(long long)grow*1024 + col];
        } else {
            int l = (i < (long long)OFF2) ? 0 : 1;
            long long j = i - (l ? (long long)OFF2 : (long long)OFF1);
            int b   = (int)(j / 147456);
            int rem = (int)(j % 147456);
            int r   = rem >> 11;
            int col = rem & 2047;
            int ih  = r >> 2;
            int CHb = (b == NB12-1) ? 16 : 18;
            if (ih >= CHb) val = 0.0f;
            else {
                int grow = (r & 3)*HD + b*18 + ih;
                if (col < 1024) val = Wih12[(long long)l*4194304 + (long long)grow*1024 + col];
                else            val = Whh12[(long long)l*4194304 + (long long)grow*1024 + (col-1024)];
            }
        }
        g_wblob[i] = __float2bfloat16(val);
    }
}

// ---------------- prep: biases, W_ih0, state/flag reset ----------------
__global__ void prep_small(const float* __restrict__ Wih0,
                           const float* __restrict__ bih0, const float* __restrict__ bhh0,
                           const float* __restrict__ bih12, const float* __restrict__ bhh12)
{
    int i = blockIdx.x*blockDim.x + threadIdx.x;
    int n = blockDim.x*gridDim.x;
    for (int k = i; k < 3*64*32; k += n) g_flag[k] = 0;
    for (int k = i; k < 3*HD; k += n) g_hall[k] = __float2bfloat16(0.0f);
    for (int k = i; k < NB0*128 + 2*NB12*72; k += n) {
        float v;
        if (k < NB0*128) {
            int b = k >> 7, r = k & 127;
            int grow = (r & 3)*HD + b*32 + (r >> 2);
            v = bih0[grow] + bhh0[grow];
        } else {
            int j  = k - NB0*128;
            int l  = j / (NB12*72);
            int jj = j - l*(NB12*72);
            int b  = jj / 72, r = jj % 72;
            int ih = r >> 2;
            int CHb = (b == NB12-1) ? 16 : 18;
            if (ih >= CHb) v = 0.0f;
            else {
                int grow = (r & 3)*HD + b*18 + ih;
                v = bih12[l*4096 + grow] + bhh12[l*4096 + grow];
            }
        }
        g_bias[k] = v;
    }
    for (int k = i; k < NB0*128*2; k += n) {
        int b = k >> 8;
        int r = (k >> 1) & 127;
        int c = k & 1;
        int grow = (r & 3)*HD + b*32 + (r >> 2);
        g_wih0[k] = Wih0[grow*2 + c];
    }
}

// ---------------- dot-product primitives (bf16x2 HFMA2) ----------------
template<int NJ>
__device__ __forceinline__ float dot_rr(const uint4* __restrict__ w, const uint4* __restrict__ v)
{
    __nv_bfloat162 z = __floats2bfloat162_rn(0.0f, 0.0f);
    __nv_bfloat162 a0 = z, a1 = z, a2 = z, a3 = z;
#pragma unroll
    for (int j = 0; j < NJ; j++) {
        a0 = __hfma2(u2b(w[j].x), u2b(v[j].x), a0);
        a1 = __hfma2(u2b(w[j].y), u2b(v[j].y), a1);
        a2 = __hfma2(u2b(w[j].z), u2b(v[j].z), a2);
        a3 = __hfma2(u2b(w[j].w), u2b(v[j].w), a3);
    }
    __nv_bfloat162 s2 = __hadd2(__hadd2(a0, a1), __hadd2(a2, a3));
    float2 f = __bfloat1622float2(s2);
    return f.x + f.y;
}

template<int NJ>
__device__ __forceinline__ float dot_sm(const uint4* __restrict__ wbase, int lane, const uint4* __restrict__ v)
{
    __nv_bfloat162 z = __floats2bfloat162_rn(0.0f, 0.0f);
    __nv_bfloat162 a0 = z, a1 = z, a2 = z, a3 = z;
#pragma unroll
    for (int j = 0; j < NJ; j++) {
        uint4 w = wbase[j*32 + lane];
        a0 = __hfma2(u2b(w.x), u2b(v[j].x), a0);
        a1 = __hfma2(u2b(w.y), u2b(v[j].y), a1);
        a2 = __hfma2(u2b(w.z), u2b(v[j].z), a2);
        a3 = __hfma2(u2b(w.w), u2b(v[j].w), a3);
    }
    __nv_bfloat162 s2 = __hadd2(__hadd2(a0, a1), __hadd2(a2, a3));
    float2 f = __bfloat1622float2(s2);
    return f.x + f.y;
}

// ---------------- persistent dataflow LSTM kernel ----------------
__global__ void __launch_bounds__(NTHR, 1) lstm_main(const float* __restrict__ x)
{
    extern __shared__ uint4 s_w4[];     // cached weight rows (k >= NRR)
    __shared__ uint4 s_v4[256];         // staged input vector (up to 2048 bf16)
    __shared__ float s_gates[128];
    __shared__ float s_bias[128];
    __shared__ float s_wih0[256];

    const int tid = threadIdx.x, lane = tid & 31, wid = tid >> 5;
    const int b = blockIdx.x;
    int layer, idx;
    if (b < NB0)             { layer = 0; idx = b; }
    else if (b < NB0+NB12)   { layer = 1; idx = b - NB0; }
    else                     { layer = 2; idx = b - (NB0+NB12); }

    int CH, hbase, R, rowU4, boff, NRR, NBown, NBlow;
    long long woff;
    if (layer == 0) {
        CH = 32; hbase = idx*32; R = 128; rowU4 = 128; NRR = 6;
        woff = (long long)idx*131072; boff = idx*128;
        NBown = NB0; NBlow = 0;
    } else {
        CH = (idx == NB12-1) ? 16 : 18; hbase = idx*18; R = 4*CH; rowU4 = 256; NRR = 3;
        woff = (long long)OFF1 + (long long)(layer-1)*SEG12 + (long long)idx*147456;
        boff = NB0*128 + (layer-1)*(NB12*72) + idx*72;
        NBown = NB12; NBlow = (layer == 1) ? NB0 : NB12;
    }
    const uint4* gw = (const uint4*)(g_wblob + woff);
    const uint4* hall4 = (const uint4*)g_hall;
    int* ownflags = &g_flag[layer*64*32];
    int* lowflags = &g_flag[(layer-1)*64*32];
    const int lowHalf = (NBlow + 1) >> 1;      // layer1: 16, layer2: 29
    const int ownHalf = (NBown + 1) >> 1;      // l12: 29

    // one-time: stage rows [NRR*NW, R) into smem
    const int smU4 = (R - NRR*NW) * rowU4;
    for (int i2 = tid; i2 < smU4; i2 += NTHR) s_w4[i2] = gw[(size_t)NRR*NW*rowU4 + i2];
    if (tid < R) s_bias[tid] = g_bias[boff + tid];
    if (layer == 0 && tid < 256) s_wih0[tid] = g_wih0[idx*256 + tid];

    // one-time: register-cache rows wid + k*NW, k < NRR (96 weight regs both layers)
    uint4 wreg[24];
    if (layer == 0) {
#pragma unroll
        for (int k = 0; k < 6; k++)
#pragma unroll
            for (int j = 0; j < 4; j++)
                wreg[k*4+j] = gw[(size_t)(wid + k*NW)*128 + j*32 + lane];
    } else {
#pragma unroll
        for (int k = 0; k < 3; k++)
#pragma unroll
            for (int j = 0; j < 8; j++)
                wreg[k*8+j] = gw[(size_t)(wid + k*NW)*256 + j*32 + lane];
    }
    float creg = 0.0f;                  // cell state, lives in warp 11's lanes
    __syncthreads();

    for (int t = 0; t < TT; ++t) {
        float x0 = 0.0f, x1 = 0.0f;
        if (layer == 0) { x0 = __ldg(&x[2*t]); x1 = __ldg(&x[2*t + 1]); }

        // ---- poll + stage: 1 flag/lane spin, staging split across warps ----
        if (layer == 0) {
            if (wid < 2) {
                wait_flags_sub(ownflags, 0, NB0, t, lane);     // 32 flags, 1/lane
                size_t ho = (size_t)t*384 + (size_t)wid*64;
                s_v4[wid*64 + lane]      = hall4[ho + lane];
                s_v4[wid*64 + lane + 32] = hall4[ho + lane + 32];
            }
        } else {
            if (wid < 2) {
                // lower flags split by NBlow (layer1: 16/16 of 32; layer2: 29/28 of 57)
                int first = wid ? lowHalf : 0;
                int cnt   = wid ? (NBlow - lowHalf) : lowHalf;
                wait_flags_sub(lowflags, first, cnt, t + 1, lane);
                size_t lo = (size_t)(t+1)*384 + (size_t)(layer-1)*128 + (size_t)wid*64;
                s_v4[wid*64 + lane]      = hall4[lo + lane];
                s_v4[wid*64 + lane + 32] = hall4[lo + lane + 32];
            } else if (wid < 4) {
                // own flags split by NBown (57: 29/28)
                int w2 = wid - 2;
                int first = w2 ? ownHalf : 0;
                int cnt   = w2 ? (NBown - ownHalf) : ownHalf;
                wait_flags_sub(ownflags, first, cnt, t, lane);
                size_t ho = (size_t)t*384 + (size_t)layer*128 + (size_t)w2*64;
                s_v4[128 + w2*64 + lane]      = hall4[ho + lane];
                s_v4[128 + w2*64 + lane + 32] = hall4[ho + lane + 32];
            }
        }
        __syncthreads();   // A: deps satisfied + vector staged

        // ---- compute rows (batched dots, then ILP-interleaved reductions) ----
        if (layer == 0) {
            uint4 vv[4];
#pragma unroll
            for (int j = 0; j < 4; j++) vv[j] = s_v4[j*32 + lane];
            float ss[11];
#pragma unroll
            for (int k = 0; k < 6; k++)
                ss[k] = dot_rr<4>(&wreg[k*4], vv);
#pragma unroll
            for (int k = 6; k < 11; k++) {
                int r = wid + k*NW;
                ss[k] = (r < 128) ? dot_sm<4>(s_w4 + (size_t)(r - 6*NW)*128, lane, vv) : 0.0f;
            }
#pragma unroll
            for (int o = 16; o; o >>= 1)
#pragma unroll
                for (int k = 0; k < 11; k++)
                    ss[k] += __shfl_xor_sync(0xffffffffu, ss[k], o);
            if (lane == 0) {
#pragma unroll
                for (int k = 0; k < 11; k++) {
                    int r = wid + k*NW;
                    if (r < 128)
                        s_gates[r] = ss[k] + s_bias[r] + s_wih0[2*r]*x0 + s_wih0[2*r+1]*x1;
                }
            }
        } else {
            uint4 vv[8];
#pragma unroll
            for (int j = 0; j < 8; j++) vv[j] = s_v4[j*32 + lane];
            float ss[6];
#pragma unroll
            for (int k = 0; k < 3; k++)
                ss[k] = dot_rr<8>(&wreg[k*8], vv);
#pragma unroll
            for (int k = 3; k < 6; k++) {
                int r = wid + k*NW;
                ss[k] = (r < R) ? dot_sm<8>(s_w4 + (size_t)(r - 3*NW)*256, lane, vv) : 0.0f;
            }
#pragma unroll
            for (int o = 16; o; o >>= 1)
#pragma unroll
                for (int k = 0; k < 6; k++)
                    ss[k] += __shfl_xor_sync(0xffffffffu, ss[k], o);
            if (lane == 0) {
#pragma unroll
                for (int k = 0; k < 6; k++) {
                    int r = wid + k*NW;
                    if (r < R) s_gates[r] = ss[k] + s_bias[r];
                }
            }
        }
        __syncthreads();   // B: gates ready

        // ---- pointwise + publish (warp 11, single publisher) ----
        if (wid == NW-1) {
            if (lane < CH) {
                float4 g = ((const float4*)s_gates)[lane];
                float ig = sigm(g.x);
                float fg = sigm(g.y);
                float gv = ftanh(g.z);
                float og = sigm(g.w);
                float c  = fg*creg + ig*gv;
                creg = c;
                g_hall[(size_t)(t+1)*3072 + (size_t)layer*1024 + hbase + lane] =
                    __float2bfloat16(og*ftanh(c));
            }
            __syncwarp();
            if (lane == 0) st_rel(&ownflags[idx*32], t + 1);
        }
    }
}

// ---------------- output head ----------------
__global__ void finalize_k(const float* __restrict__ Wres, const float* __restrict__ bres,
                           float* __restrict__ out)
{
    __shared__ float sred[4];
    const int t = blockIdx.x;
    const int tid = threadIdx.x;
    const __nv_bfloat16* h = g_hall + (size_t)(t+1)*3072 + 2048;
    float s = 0.0f;
    for (int k = tid; k < HD; k += 128) s += __bfloat162float(h[k]) * Wres[k];
#pragma unroll
    for (int o = 16; o; o >>= 1) s += __shfl_xor_sync(0xffffffffu, s, o);
    if ((tid & 31) == 0) sred[tid >> 5] = s;
    __syncthreads();
    if (tid == 0) {
        float tot = sred[0] + sred[1] + sred[2] + sred[3];
        out[t] = 1.0f/(1.0f + __expf(-(tot + bres[0])));
    }
}

// ---------------- launch ----------------
extern "C" void kernel_launch(void* const* d_in, const int* in_sizes, int n_in,
                              void* d_out, int out_size)
{
    const float* x     = (const float*)d_in[0];
    const float* Wih0  = (const float*)d_in[1];
    const float* Whh0  = (const float*)d_in[2];
    const float* bih0  = (const float*)d_in[3];
    const float* bhh0  = (const float*)d_in[4];
    const float* Wih12 = (const float*)d_in[5];
    const float* Whh12 = (const float*)d_in[6];
    const float* bih12 = (const float*)d_in[7];
    const float* bhh12 = (const float*)d_in[8];
    const float* Wres  = (const float*)d_in[9];
    const float* bres  = (const float*)d_in[10];
    float* out = (float*)d_out;

    cudaFuncSetAttribute(lstm_main, cudaFuncAttributeMaxDynamicSharedMemorySize, DSMEM_BYTES);

    prep_small<<<26, 256>>>(Wih0, bih0, bhh0, bih12, bhh12);
    prep_w<<<2048, 256>>>(Whh0, Wih12, Whh12);
    lstm_main<<<GRIDN, NTHR, DSMEM_BYTES>>>(x);
    finalize_k<<<TT, 128>>>(Wres, bres, out);
}